// round 1
// baseline (speedup 1.0000x reference)
#include <cuda_runtime.h>
#include <cstdint>
#include <cstdio>

#define NN 100000
#define EE 1600000

// ---------------------------------------------------------------------------
// Static device scratch (no allocation allowed).
// ---------------------------------------------------------------------------
__device__ __align__(256) float g_deg[NN];          // deg -> dinv (in place)
__device__ __align__(256) float g_en [EE];          // edge_norm
__device__ __align__(256) float g_xp [NN * 36];     // x padded 35->36
__device__ __align__(256) float g_p0 [NN * 36];     // agg(x)
__device__ __align__(256) float g_a1 [NN * 336];    // relu(conv1)
__device__ __align__(256) float g_t2 [NN * 168];    // a1 @ W2
__device__ __align__(256) float g_p2 [NN * 168];    // agg(t2)
__device__ __align__(256) float g_t3 [NN * 84];
__device__ __align__(256) float g_p3 [NN * 84];
__device__ __align__(256) float g_t4 [NN * 42];
__device__ __align__(256) float g_p4 [NN * 42];
__device__ __align__(256) float g_a4 [NN * 42];     // relu(p4 + b4)
__device__ __align__(256) float g_p5 [NN * 42];     // agg(a4)

// ---------------------------------------------------------------------------
// Vector reductions (sm_90+ / sm_103a: vector f32 red)
// ---------------------------------------------------------------------------
__device__ __forceinline__ void red_add4(float* a, float4 v) {
    asm volatile("red.global.add.v4.f32 [%0], {%1,%2,%3,%4};"
                 :: "l"(a), "f"(v.x), "f"(v.y), "f"(v.z), "f"(v.w) : "memory");
}
__device__ __forceinline__ void red_add2(float* a, float2 v) {
    asm volatile("red.global.add.v2.f32 [%0], {%1,%2};"
                 :: "l"(a), "f"(v.x), "f"(v.y) : "memory");
}

// ---------------------------------------------------------------------------
// Degree / normalization
// ---------------------------------------------------------------------------
__global__ void k_deg_init(float* deg) {
    int i = blockIdx.x * blockDim.x + threadIdx.x;
    if (i < NN) deg[i] = 1.0f;   // self loop
}
__global__ void k_deg_count(const int* __restrict__ dst, float* deg) {
    int e = blockIdx.x * blockDim.x + threadIdx.x;
    if (e < EE) atomicAdd(&deg[dst[e]], 1.0f);
}
__global__ void k_rsqrt(float* deg) {
    int i = blockIdx.x * blockDim.x + threadIdx.x;
    if (i < NN) deg[i] = rsqrtf(deg[i]);
}
__global__ void k_edge_norm(const int* __restrict__ src, const int* __restrict__ dst,
                            const float* __restrict__ dinv, float* __restrict__ en) {
    int e = blockIdx.x * blockDim.x + threadIdx.x;
    if (e < EE) en[e] = dinv[src[e]] * dinv[dst[e]];
}

// pad x [N,35] -> xp [N,36] (zero last col)
__global__ void k_pad(const float* __restrict__ x, float* __restrict__ xp) {
    int i = blockIdx.x * blockDim.x + threadIdx.x;
    if (i >= NN * 36) return;
    int n = i / 36, c = i - n * 36;
    xp[i] = (c < 35) ? x[(size_t)n * 35 + c] : 0.0f;
}

// p = t * dinv^2  (self-loop contribution; scatter adds the rest)
template <int D>
__global__ void k_pinit(const float* __restrict__ t, const float* __restrict__ dinv,
                        float* __restrict__ p) {
    int i = blockIdx.x * blockDim.x + threadIdx.x;
    if (i >= NN * D) return;
    int n = i / D;
    float s = dinv[n];
    p[i] = t[i] * s * s;
}

// a = relu(p + b)   (D-wide bias)
template <int D>
__global__ void k_relu_bias(const float* __restrict__ p, const float* __restrict__ b,
                            float* __restrict__ a) {
    int i = blockIdx.x * blockDim.x + threadIdx.x;
    if (i >= NN * D) return;
    a[i] = fmaxf(p[i] + b[i % D], 0.0f);
}

// ---------------------------------------------------------------------------
// Edge scatter: p[dst] += t[src] * en[e], vectorized atomics.
// GROUP = D/VEC consecutive lanes handle one edge; blockDim = 252 (divisible
// by all GROUP values used: 9, 42, 21).
// ---------------------------------------------------------------------------
template <int D, int VEC>
__global__ void __launch_bounds__(252)
k_scatter(const int* __restrict__ src, const int* __restrict__ dst,
          const float* __restrict__ en, const float* __restrict__ t,
          float* __restrict__ p) {
    constexpr int GROUP = D / VEC;
    constexpr int EPB = 252 / GROUP;
    int lane = threadIdx.x;
    int g = lane / GROUP;
    int c = lane - g * GROUP;
    long e = (long)blockIdx.x * EPB + g;
    if (e >= EE) return;
    int s = src[e];
    int d = dst[e];
    float w = en[e];
    if (VEC == 4) {
        float4 v = *(const float4*)(t + (size_t)s * D + c * 4);
        v.x *= w; v.y *= w; v.z *= w; v.w *= w;
        red_add4(p + (size_t)d * D + c * 4, v);
    } else {
        float2 v = *(const float2*)(t + (size_t)s * D + c * 2);
        v.x *= w; v.y *= w;
        red_add2(p + (size_t)d * D + c * 2, v);
    }
}

// ---------------------------------------------------------------------------
// Generic fp32 GEMM: C[M,Nd] = f(A[M,lda(:K)] (+binA, relu)) @ B[K,Nd] (+bout, relu)
// 64x64 tile, 256 threads, 4x4 microtile, BK=16.
// ---------------------------------------------------------------------------
template <bool IN_RELU, bool EPI>
__global__ void __launch_bounds__(256)
k_gemm(const float* __restrict__ A, int lda, const float* __restrict__ binA,
       const float* __restrict__ B, const float* __restrict__ bout,
       float* __restrict__ C, int M, int K, int Nd) {
    __shared__ float As[64][16];
    __shared__ float Bs[16][64];

    int tid = threadIdx.x;
    int tx = tid & 15;        // 0..15 -> 4 cols each
    int ty = tid >> 4;        // 0..15 -> 4 rows each
    int row0 = blockIdx.x * 64;
    int col0 = blockIdx.y * 64;

    float acc[4][4] = {};

    for (int k0 = 0; k0 < K; k0 += 16) {
        // load A tile 64x16
#pragma unroll
        for (int l = 0; l < 4; l++) {
            int idx = tid + l * 256;
            int r = idx >> 4, kk = idx & 15;
            int grow = row0 + r, gk = k0 + kk;
            float a = 0.0f;
            if (grow < M && gk < K) {
                a = A[(size_t)grow * lda + gk];
                if (IN_RELU) a = fmaxf(a + binA[gk], 0.0f);
            }
            As[r][kk] = a;
        }
        // load B tile 16x64
#pragma unroll
        for (int l = 0; l < 4; l++) {
            int idx = tid + l * 256;
            int kk = idx >> 6, cc = idx & 63;
            int gk = k0 + kk, gc = col0 + cc;
            Bs[kk][cc] = (gk < K && gc < Nd) ? B[(size_t)gk * Nd + gc] : 0.0f;
        }
        __syncthreads();
#pragma unroll
        for (int kk = 0; kk < 16; kk++) {
            float4 bv = *(const float4*)&Bs[kk][tx * 4];
#pragma unroll
            for (int i = 0; i < 4; i++) {
                float a = As[ty * 4 + i][kk];
                acc[i][0] += a * bv.x;
                acc[i][1] += a * bv.y;
                acc[i][2] += a * bv.z;
                acc[i][3] += a * bv.w;
            }
        }
        __syncthreads();
    }
#pragma unroll
    for (int i = 0; i < 4; i++) {
        int row = row0 + ty * 4 + i;
        if (row >= M) continue;
#pragma unroll
        for (int j = 0; j < 4; j++) {
            int col = col0 + tx * 4 + j;
            if (col >= Nd) continue;
            float v = acc[i][j];
            if (EPI) v = fmaxf(v + bout[col], 0.0f);
            C[(size_t)row * Nd + col] = v;
        }
    }
}

// ---------------------------------------------------------------------------
// Final fused head: mu/logstd GEMV (K=42 -> 21 each), reparam, log_softmax.
// One thread per node; weights in smem (broadcast reads).
// ---------------------------------------------------------------------------
__global__ void __launch_bounds__(128)
k_final(const float* __restrict__ p5,
        const float* __restrict__ Wmu, const float* __restrict__ bmu,
        const float* __restrict__ Wls, const float* __restrict__ bls,
        const float* __restrict__ eps, float* __restrict__ out) {
    __shared__ float sWmu[42 * 21];
    __shared__ float sWls[42 * 21];
    __shared__ float sbmu[21];
    __shared__ float sbls[21];
    for (int i = threadIdx.x; i < 42 * 21; i += blockDim.x) {
        sWmu[i] = Wmu[i];
        sWls[i] = Wls[i];
    }
    if (threadIdx.x < 21) {
        sbmu[threadIdx.x] = bmu[threadIdx.x];
        sbls[threadIdx.x] = bls[threadIdx.x];
    }
    __syncthreads();

    int n = blockIdx.x * blockDim.x + threadIdx.x;
    if (n >= NN) return;

    float xr[42];
#pragma unroll
    for (int i = 0; i < 42; i++) xr[i] = p5[(size_t)n * 42 + i];

    float z[21];
#pragma unroll
    for (int j = 0; j < 21; j++) {
        float mu = sbmu[j];
        float ls = sbls[j];
#pragma unroll
        for (int i = 0; i < 42; i++) {
            mu += xr[i] * sWmu[i * 21 + j];
            ls += xr[i] * sWls[i * 21 + j];
        }
        ls = fminf(ls, 10.0f);
        z[j] = mu + eps[(size_t)n * 21 + j] * expf(ls);
    }
    float m = z[0];
#pragma unroll
    for (int j = 1; j < 21; j++) m = fmaxf(m, z[j]);
    float s = 0.0f;
#pragma unroll
    for (int j = 0; j < 21; j++) s += expf(z[j] - m);
    float lse = m + logf(s);
#pragma unroll
    for (int j = 0; j < 21; j++) out[(size_t)n * 21 + j] = z[j] - lse;
}

// ---------------------------------------------------------------------------
static inline int cdiv(long a, long b) { return (int)((a + b - 1) / b); }

extern "C" void kernel_launch(void* const* d_in, const int* in_sizes, int n_in,
                              void* d_out, int out_size) {
    const float* x    = (const float*)d_in[0];
    const int*   ei   = (const int*)  d_in[1];
    const float* eps  = (const float*)d_in[2];
    const float* W1   = (const float*)d_in[3];
    const float* b1   = (const float*)d_in[4];
    const float* W2   = (const float*)d_in[5];
    const float* b2   = (const float*)d_in[6];
    const float* W3   = (const float*)d_in[7];
    const float* b3   = (const float*)d_in[8];
    const float* W4   = (const float*)d_in[9];
    const float* b4   = (const float*)d_in[10];
    const float* Wmu  = (const float*)d_in[11];
    const float* bmu  = (const float*)d_in[12];
    const float* Wls  = (const float*)d_in[13];
    const float* bls  = (const float*)d_in[14];
    float* out = (float*)d_out;

    float *deg, *en, *xp, *p0, *a1, *t2, *p2, *t3, *p3, *t4, *p4, *a4, *p5;
    cudaGetSymbolAddress((void**)&deg, g_deg);
    cudaGetSymbolAddress((void**)&en,  g_en);
    cudaGetSymbolAddress((void**)&xp,  g_xp);
    cudaGetSymbolAddress((void**)&p0,  g_p0);
    cudaGetSymbolAddress((void**)&a1,  g_a1);
    cudaGetSymbolAddress((void**)&t2,  g_t2);
    cudaGetSymbolAddress((void**)&p2,  g_p2);
    cudaGetSymbolAddress((void**)&t3,  g_t3);
    cudaGetSymbolAddress((void**)&p3,  g_p3);
    cudaGetSymbolAddress((void**)&t4,  g_t4);
    cudaGetSymbolAddress((void**)&p4,  g_p4);
    cudaGetSymbolAddress((void**)&a4,  g_a4);
    cudaGetSymbolAddress((void**)&p5,  g_p5);

    const int* src = ei;
    const int* dst = ei + EE;

    // normalization
    k_deg_init<<<cdiv(NN, 256), 256>>>(deg);
    k_deg_count<<<cdiv(EE, 256), 256>>>(dst, deg);
    k_rsqrt<<<cdiv(NN, 256), 256>>>(deg);
    k_edge_norm<<<cdiv(EE, 256), 256>>>(src, dst, deg, en);

    // conv1: propagate x (padded to 36) first, then GEMM 35->336 (+b1, relu)
    k_pad<<<cdiv((long)NN * 36, 256), 256>>>(x, xp);
    k_pinit<36><<<cdiv((long)NN * 36, 256), 256>>>(xp, deg, p0);
    k_scatter<36, 4><<<cdiv(EE, 28), 252>>>(src, dst, en, xp, p0);
    k_gemm<false, true><<<dim3(cdiv(NN, 64), 6), 256>>>(p0, 36, nullptr, W1, b1, a1, NN, 35, 336);

    // conv2: transform first (336->168), then propagate
    k_gemm<false, false><<<dim3(cdiv(NN, 64), 3), 256>>>(a1, 336, nullptr, W2, nullptr, t2, NN, 336, 168);
    k_pinit<168><<<cdiv((long)NN * 168, 256), 256>>>(t2, deg, p2);
    k_scatter<168, 4><<<cdiv(EE, 6), 252>>>(src, dst, en, t2, p2);

    // conv3: input = relu(p2 + b2) fused into GEMM (168->84)
    k_gemm<true, false><<<dim3(cdiv(NN, 64), 2), 256>>>(p2, 168, b2, W3, nullptr, t3, NN, 168, 84);
    k_pinit<84><<<cdiv((long)NN * 84, 256), 256>>>(t3, deg, p3);
    k_scatter<84, 4><<<cdiv(EE, 12), 252>>>(src, dst, en, t3, p3);

    // conv4: input = relu(p3 + b3), 84->42
    k_gemm<true, false><<<dim3(cdiv(NN, 64), 1), 256>>>(p3, 84, b3, W4, nullptr, t4, NN, 84, 42);
    k_pinit<42><<<cdiv((long)NN * 42, 256), 256>>>(t4, deg, p4);
    k_scatter<42, 2><<<cdiv(EE, 12), 252>>>(src, dst, en, t4, p4);

    // a4 = relu(p4 + b4); shared propagation for mu/logstd heads
    k_relu_bias<42><<<cdiv((long)NN * 42, 256), 256>>>(p4, b4, a4);
    k_pinit<42><<<cdiv((long)NN * 42, 256), 256>>>(a4, deg, p5);
    k_scatter<42, 2><<<cdiv(EE, 12), 252>>>(src, dst, en, a4, p5);

    // fused heads + reparam + log_softmax
    k_final<<<cdiv(NN, 128), 128>>>(p5, Wmu, bmu, Wls, bls, eps, out);
}